// round 1
// baseline (speedup 1.0000x reference)
#include <cuda_runtime.h>
#include <cuda_bf16.h>

// Problem constants: B=16, C=512, H=W=32, P=1024, GROUPS=32
#define BB 16
#define CC 512
#define PP 1024

// Scratch (static device memory; allocation-free per harness rules)
__device__ __align__(128) float g_n[BB * CC * PP];     // groupnorm output
__device__ __align__(128) float g_q[BB * CC * PP];
__device__ __align__(128) float g_k[BB * CC * PP];
__device__ __align__(128) float g_v[BB * CC * PP];
__device__ __align__(128) float g_s[(size_t)BB * PP * PP];   // score matrix
__device__ __align__(128) float g_diag[BB * PP];             // diag[b, i*32+j] == diag[b, p]

// ---------------------------------------------------------------------------
// GroupNorm: one block per (b, group). Group = 16 channels x 1024 = 16384 elems.
// ---------------------------------------------------------------------------
__global__ void gn_kernel(const float* __restrict__ x, float* __restrict__ out)
{
    int b = blockIdx.x >> 5;
    int g = blockIdx.x & 31;
    const float* xp = x + ((size_t)b * CC + g * 16) * PP;
    float* op = out + ((size_t)b * CC + g * 16) * PP;

    float s = 0.f, s2 = 0.f;
    for (int i = threadIdx.x; i < 16384; i += 256) {
        float v = xp[i];
        s += v;
        s2 += v * v;
    }
    __shared__ float sh1[256], sh2[256];
    sh1[threadIdx.x] = s;
    sh2[threadIdx.x] = s2;
    __syncthreads();
    for (int off = 128; off; off >>= 1) {
        if (threadIdx.x < off) {
            sh1[threadIdx.x] += sh1[threadIdx.x + off];
            sh2[threadIdx.x] += sh2[threadIdx.x + off];
        }
        __syncthreads();
    }
    float mean = sh1[0] * (1.f / 16384.f);
    float var  = sh2[0] * (1.f / 16384.f) - mean * mean;
    float inv  = rsqrtf(var + 1e-5f);
    for (int i = threadIdx.x; i < 16384; i += 256)
        op[i] = (xp[i] - mean) * inv;
}

// ---------------------------------------------------------------------------
// Generic batched "TN" GEMM: both operands stored K-major.
//   C[m,n] = sum_k A[k*lda + m] * B[k*ldb + n]
// MODE 0: out = acc + bias[m]                       (q/k/v projections)
// MODE 1: out = acc                                 (score matrix S)
// MODE 2: out = xres + bias[m] + diag[n] * acc      (final fused epilogue)
// Tile: BM=BN=64, BK=16, 256 threads, 4x4 per thread.
// ---------------------------------------------------------------------------
template <int MODE>
__global__ __launch_bounds__(256)
void gemm_tn(const float* __restrict__ A, const float* __restrict__ Bm,
             float* __restrict__ C, int M, int N, int K,
             int lda, int ldb, int ldc,
             long long sA, long long sB, long long sC,
             const float* __restrict__ bias,
             const float* __restrict__ xres,
             const float* __restrict__ dg)
{
    int bz = blockIdx.z;
    A  += (long long)bz * sA;
    Bm += (long long)bz * sB;
    C  += (long long)bz * sC;

    int m0 = blockIdx.x * 64;
    int n0 = blockIdx.y * 64;

    __shared__ float As[16][64];
    __shared__ float Bs[16][64];

    int t  = threadIdx.x;
    int kk = t >> 4;           // 0..15 (k row for loads)
    int q4 = (t & 15) << 2;    // 0,4,...,60 (column quad for loads)
    int ty = t >> 4;           // 0..15 (compute row group)
    int tx = t & 15;           // 0..15 (compute col group)

    float acc[4][4];
#pragma unroll
    for (int r = 0; r < 4; r++)
#pragma unroll
        for (int c = 0; c < 4; c++) acc[r][c] = 0.f;

    for (int k0 = 0; k0 < K; k0 += 16) {
        *(float4*)&As[kk][q4] = *(const float4*)&A[(size_t)(k0 + kk) * lda + m0 + q4];
        *(float4*)&Bs[kk][q4] = *(const float4*)&Bm[(size_t)(k0 + kk) * ldb + n0 + q4];
        __syncthreads();
#pragma unroll
        for (int kq = 0; kq < 16; kq++) {
            float a[4], bb[4];
#pragma unroll
            for (int r = 0; r < 4; r++) a[r] = As[kq][ty * 4 + r];
#pragma unroll
            for (int c = 0; c < 4; c++) bb[c] = Bs[kq][tx * 4 + c];
#pragma unroll
            for (int r = 0; r < 4; r++)
#pragma unroll
                for (int c = 0; c < 4; c++)
                    acc[r][c] += a[r] * bb[c];
        }
        __syncthreads();
    }

    const float* xr = (MODE == 2) ? (xres + (long long)bz * sC) : nullptr;
    const float* dgb = (MODE == 2) ? (dg + bz * PP) : nullptr;

#pragma unroll
    for (int r = 0; r < 4; r++) {
        int m = m0 + ty * 4 + r;
        float bv = (MODE == 0 || MODE == 2) ? bias[m] : 0.f;
#pragma unroll
        for (int c = 0; c < 4; c++) {
            int n = n0 + tx * 4 + c;
            float v = acc[r][c];
            if (MODE == 0) v += bv;
            if (MODE == 2) v = xr[(size_t)m * ldc + n] + bv + dgb[n] * v;
            C[(size_t)m * ldc + n] = v;
        }
    }
}

// ---------------------------------------------------------------------------
// Softmax denominators + diag gather.
// Block per (b, i). For h in 0..31 read row p = h*32+i of S[b], accumulate
// exp(scale*S) into per-j bins (j = p' & 31; each thread owns one j since
// blockDim=256 and 256 % 32 == 0). Capture numerator at (p=33i, p'=33j).
// diag[b, i*32+j] = num / denom.
// ---------------------------------------------------------------------------
__global__ void softmax_diag_kernel(const float* __restrict__ S,
                                    float* __restrict__ diag)
{
    const float scale = 0.04419417382415922f;   // 512^-0.5
    int b = blockIdx.x >> 5;
    int i = blockIdx.x & 31;
    const float* Sb = S + (size_t)b * PP * PP;

    __shared__ float num_sh[32];
    __shared__ float red[256];

    float acc = 0.f;
    for (int h = 0; h < 32; h++) {
        const float* row = Sb + (size_t)(h * 32 + i) * PP;
        bool diag_row = (h == i);
        for (int p = threadIdx.x; p < PP; p += 256) {
            float e = __expf(scale * row[p]);
            acc += e;
            if (diag_row && ((p >> 5) == (p & 31)))
                num_sh[p & 31] = e;   // p == 33*j
        }
    }
    red[threadIdx.x] = acc;
    __syncthreads();
    // Reduce preserving tid%32 classes: red[j] = sum over threads with tid%32==j
    for (int off = 128; off >= 32; off >>= 1) {
        if (threadIdx.x < off) red[threadIdx.x] += red[threadIdx.x + off];
        __syncthreads();
    }
    if (threadIdx.x < 32)
        diag[(size_t)blockIdx.x * 32 + threadIdx.x] =
            num_sh[threadIdx.x] / red[threadIdx.x];
}

// ---------------------------------------------------------------------------
// kernel_launch
// Inputs (metadata order): x, Wq, bq, Wk, bk, Wv, bv, Wn, bn
// ---------------------------------------------------------------------------
extern "C" void kernel_launch(void* const* d_in, const int* in_sizes, int n_in,
                              void* d_out, int out_size)
{
    const float* x  = (const float*)d_in[0];
    const float* Wq = (const float*)d_in[1];
    const float* bq = (const float*)d_in[2];
    const float* Wk = (const float*)d_in[3];
    const float* bk = (const float*)d_in[4];
    const float* Wv = (const float*)d_in[5];
    const float* bv = (const float*)d_in[6];
    const float* Wn = (const float*)d_in[7];
    const float* bn = (const float*)d_in[8];
    float* out = (float*)d_out;

    float *pn, *pq, *pk, *pv, *ps, *pd;
    cudaGetSymbolAddress((void**)&pn, g_n);
    cudaGetSymbolAddress((void**)&pq, g_q);
    cudaGetSymbolAddress((void**)&pk, g_k);
    cudaGetSymbolAddress((void**)&pv, g_v);
    cudaGetSymbolAddress((void**)&ps, g_s);
    cudaGetSymbolAddress((void**)&pd, g_diag);

    const long long sCP = (long long)CC * PP;   // 512*1024
    const long long sSS = (long long)PP * PP;   // 1024*1024

    // 1. GroupNorm
    gn_kernel<<<BB * 32, 256>>>(x, pn);

    // 2. Projections q, k, v : M=512, N=1024, K=512 per batch
    dim3 gproj(CC / 64, PP / 64, BB);
    gemm_tn<0><<<gproj, 256>>>(Wq, pn, pq, CC, PP, CC, CC, PP, PP,
                               0, sCP, sCP, bq, nullptr, nullptr);
    gemm_tn<0><<<gproj, 256>>>(Wk, pn, pk, CC, PP, CC, CC, PP, PP,
                               0, sCP, sCP, bk, nullptr, nullptr);
    gemm_tn<0><<<gproj, 256>>>(Wv, pn, pv, CC, PP, CC, CC, PP, PP,
                               0, sCP, sCP, bv, nullptr, nullptr);

    // 3. Scores S = Q^T K : M=N=1024, K=512 per batch
    dim3 gs(PP / 64, PP / 64, BB);
    gemm_tn<1><<<gs, 256>>>(pq, pk, ps, PP, PP, CC, PP, PP, PP,
                            sCP, sCP, sSS, nullptr, nullptr, nullptr);

    // 4. Softmax denominators + diag gather
    softmax_diag_kernel<<<BB * 32, 256>>>(ps, pd);

    // 5. Final projection fused with diag scaling + residual + bias
    gemm_tn<2><<<gproj, 256>>>(Wn, pv, out, CC, PP, CC, CC, PP, PP,
                               0, sCP, sCP, bn, x, pd);
}

// round 3
// speedup vs baseline: 4.9017x; 4.9017x over previous
#include <cuda_runtime.h>
#include <cuda_bf16.h>
#include <cstdint>

#define BB 16
#define CC 512
#define PP 1024

typedef __nv_bfloat16 bf16;

// ---------------------------------------------------------------------------
// Static device scratch (no allocation allowed)
// ---------------------------------------------------------------------------
__device__ __align__(1024) bf16 g_nT[(size_t)BB * PP * CC];   // [b][p][c]
__device__ __align__(1024) bf16 g_qT[(size_t)BB * PP * CC];   // [b][p][o]
__device__ __align__(1024) bf16 g_kT[(size_t)BB * PP * CC];
__device__ __align__(1024) bf16 g_vT[(size_t)BB * PP * CC];
__device__ __align__(1024) bf16 g_WT[4 * CC * CC];            // [which][o][c]
__device__ __align__(128)  float g_S[(size_t)BB * PP * PP];   // scores fp32
__device__ __align__(128)  float g_diag[BB * PP];

// ---------------------------------------------------------------------------
// helpers
// ---------------------------------------------------------------------------
__device__ __forceinline__ uint32_t smem_u32(const void* p) {
    uint32_t a;
    asm("{ .reg .u64 t; cvta.to.shared.u64 t, %1; cvt.u32.u64 %0, t; }"
        : "=r"(a) : "l"(p));
    return a;
}

#define CPA16(sm, gm) \
    asm volatile("cp.async.cg.shared.global [%0], [%1], 16;" \
                 :: "r"(sm), "l"(gm))

__device__ __forceinline__ void ldsm4(uint32_t* r, uint32_t a) {
    asm volatile("ldmatrix.sync.aligned.m8n8.x4.shared.b16 {%0,%1,%2,%3}, [%4];"
                 : "=r"(r[0]), "=r"(r[1]), "=r"(r[2]), "=r"(r[3]) : "r"(a));
}

__device__ __forceinline__ void mma16816(float* c, const uint32_t* a,
                                         uint32_t b0, uint32_t b1) {
    asm volatile(
        "mma.sync.aligned.m16n8k16.row.col.f32.bf16.bf16.f32 "
        "{%0,%1,%2,%3}, {%4,%5,%6,%7}, {%8,%9}, {%0,%1,%2,%3};"
        : "+f"(c[0]), "+f"(c[1]), "+f"(c[2]), "+f"(c[3])
        : "r"(a[0]), "r"(a[1]), "r"(a[2]), "r"(a[3]), "r"(b0), "r"(b1));
}

// smem tile: 128 rows x 80 bytes (64B data + 16B pad) -> conflict-free ldmatrix
#define ROWB   80
#define TILEB  (128 * ROWB)          // 10240
#define STAGES 3
#define SMEM_BYTES (STAGES * 2 * TILEB)   // 61440

// ---------------------------------------------------------------------------
// Weight transpose: WT[o][c] = bf16(W[c][o])
// ---------------------------------------------------------------------------
__global__ void wt_kernel(const float* __restrict__ Wq, const float* __restrict__ Wk,
                          const float* __restrict__ Wv, const float* __restrict__ Wn,
                          bf16* __restrict__ WT)
{
    const float* srcs[4] = {Wq, Wk, Wv, Wn};
    const float* W = srcs[blockIdx.z];
    bf16* dst = WT + (size_t)blockIdx.z * CC * CC;
    __shared__ float t[32][33];
    int c0 = blockIdx.x * 32, o0 = blockIdx.y * 32;
    for (int i = threadIdx.y; i < 32; i += 8)
        t[i][threadIdx.x] = W[(size_t)(c0 + i) * CC + o0 + threadIdx.x];
    __syncthreads();
    for (int i = threadIdx.y; i < 32; i += 8)
        dst[(size_t)(o0 + i) * CC + c0 + threadIdx.x] =
            __float2bfloat16(t[threadIdx.x][i]);
}

// ---------------------------------------------------------------------------
// GroupNorm -> transposed bf16 output nT[b][p][c]
// ---------------------------------------------------------------------------
__global__ void gn_kernel(const float* __restrict__ x, bf16* __restrict__ nT)
{
    int b = blockIdx.x >> 5;
    int g = blockIdx.x & 31;
    const float* xp = x + ((size_t)b * CC + g * 16) * PP;

    float s = 0.f, s2 = 0.f;
    for (int i = threadIdx.x; i < 16384; i += 256) {
        float v = xp[i];
        s += v; s2 += v * v;
    }
    __shared__ float sh1[256], sh2[256];
    sh1[threadIdx.x] = s; sh2[threadIdx.x] = s2;
    __syncthreads();
    for (int off = 128; off; off >>= 1) {
        if (threadIdx.x < off) {
            sh1[threadIdx.x] += sh1[threadIdx.x + off];
            sh2[threadIdx.x] += sh2[threadIdx.x + off];
        }
        __syncthreads();
    }
    float mean = sh1[0] * (1.f / 16384.f);
    float var  = sh2[0] * (1.f / 16384.f) - mean * mean;
    float inv  = rsqrtf(var + 1e-5f);

    bf16* np = nT + (size_t)b * PP * CC + g * 16;
    for (int p = threadIdx.x; p < PP; p += 256) {
        uint32_t pk[8];
#pragma unroll
        for (int cc = 0; cc < 16; cc += 2) {
            float v0 = (xp[(size_t)cc * PP + p] - mean) * inv;
            float v1 = (xp[(size_t)(cc + 1) * PP + p] - mean) * inv;
            __nv_bfloat162 h = __floats2bfloat162_rn(v0, v1);
            pk[cc >> 1] = *(uint32_t*)&h;
        }
        uint4* dst = (uint4*)(np + (size_t)p * CC);
        dst[0] = make_uint4(pk[0], pk[1], pk[2], pk[3]);
        dst[1] = make_uint4(pk[4], pk[5], pk[6], pk[7]);
    }
}

// ---------------------------------------------------------------------------
// HMMA GEMM: D[m][n] = sum_k A[m][k] * B[n][k], both operands K-contig (lda=512)
// CTA tile 128x128, warp tile 32x64, K slab 32, 3-stage cp.async.
// MODE 0: bf16 Cout[m][n] = D + bias[n]            (projections)
// MODE 1: fp32 Cout[m][n] = D                      (scores)
// MODE 2: fp32 out[n][m]  = x[n][m] + bias[n] + diag[m]*D   (final)
// ---------------------------------------------------------------------------
template <int MODE>
__global__ __launch_bounds__(256)
void gemm_mma(const bf16* __restrict__ A, const bf16* __restrict__ Bm,
              long long strideB, void* __restrict__ Cout,
              const float* __restrict__ bias, const float* __restrict__ xres,
              const float* __restrict__ dgv)
{
    extern __shared__ char smem[];
    uint32_t s0 = smem_u32(smem);

    int tid = threadIdx.x, lane = tid & 31, wid = tid >> 5;
    int wm = wid & 3, wn = wid >> 2;
    int b = blockIdx.z;
    int m0 = blockIdx.x * 128, n0 = blockIdx.y * 128;

    const char* Ab = (const char*)(A + (size_t)b * ((size_t)PP * CC) + (size_t)m0 * CC);
    const char* Bb = (const char*)(Bm + (size_t)b * strideB + (size_t)n0 * CC);

    // load mapping: 512 16B-chunks per operand tile, 2 per thread
    int id0 = tid, id1 = tid + 256;
    int ra0 = id0 >> 2, ca0 = id0 & 3;
    int ra1 = id1 >> 2, ca1 = id1 & 3;
    uint32_t sA0 = (uint32_t)(ra0 * ROWB + ca0 * 16);
    uint32_t sA1 = (uint32_t)(ra1 * ROWB + ca1 * 16);
    int gA0 = ra0 * 1024 + ca0 * 16;   // bytes: row*512*2 + chunk*16
    int gA1 = ra1 * 1024 + ca1 * 16;

    // ldmatrix lane addressing (relative to stage base)
    uint32_t aoff[2][2], boff[2][4];
    {
        int ar = wm * 32 + (lane & 15);
        int ac = (lane >> 4);            // 0/1 -> k sub-chunk
#pragma unroll
        for (int mr = 0; mr < 2; mr++)
#pragma unroll
            for (int ks = 0; ks < 2; ks++)
                aoff[mr][ks] = (uint32_t)((ar + mr * 16) * ROWB + (ks * 2 + ac) * 16);
        int br = wn * 64 + ((lane >> 4) & 1) * 8 + (lane & 7);
        int bc = (lane >> 3) & 1;
#pragma unroll
        for (int ks = 0; ks < 2; ks++)
#pragma unroll
            for (int p = 0; p < 4; p++)
                boff[ks][p] = (uint32_t)((br + p * 16) * ROWB + (ks * 2 + bc) * 16);
    }

    float acc[2][8][4];
#pragma unroll
    for (int i = 0; i < 2; i++)
#pragma unroll
        for (int j = 0; j < 8; j++)
#pragma unroll
            for (int l = 0; l < 4; l++) acc[i][j][l] = 0.f;

    auto issue = [&](int s, int st) {
        uint32_t ab = s0 + (uint32_t)st * (2 * TILEB);
        uint32_t bb = ab + TILEB;
        const char* ga = Ab + s * 64;
        const char* gb = Bb + s * 64;
        CPA16(ab + sA0, ga + gA0);
        CPA16(ab + sA1, ga + gA1);
        CPA16(bb + sA0, gb + gA0);
        CPA16(bb + sA1, gb + gA1);
        asm volatile("cp.async.commit_group;" ::: "memory");
    };

    issue(0, 0);
    issue(1, 1);

    for (int s = 0; s < 16; s++) {
        if (s < 15) asm volatile("cp.async.wait_group 1;" ::: "memory");
        else        asm volatile("cp.async.wait_group 0;" ::: "memory");
        __syncthreads();
        if (s + 2 < 16) issue(s + 2, (s + 2) % 3);

        uint32_t ab = s0 + (uint32_t)(s % 3) * (2 * TILEB);
        uint32_t bb = ab + TILEB;

#pragma unroll
        for (int ks = 0; ks < 2; ks++) {
            uint32_t af[2][4], bf[4][4];
            ldsm4(af[0], ab + aoff[0][ks]);
            ldsm4(af[1], ab + aoff[1][ks]);
#pragma unroll
            for (int p = 0; p < 4; p++)
                ldsm4(bf[p], bb + boff[ks][p]);
#pragma unroll
            for (int mr = 0; mr < 2; mr++)
#pragma unroll
                for (int nt = 0; nt < 8; nt++)
                    mma16816(acc[mr][nt], af[mr],
                             bf[nt >> 1][(nt & 1) * 2], bf[nt >> 1][(nt & 1) * 2 + 1]);
        }
        __syncthreads();
    }

    // ---------------- epilogue ----------------
    int row0 = m0 + wm * 32;
    int col0 = n0 + wn * 64;
    int tr = lane >> 2, tc = (lane & 3) * 2;

    if (MODE == 0) {
        bf16* Cb = (bf16*)Cout + (size_t)b * ((size_t)PP * CC);
#pragma unroll
        for (int mr = 0; mr < 2; mr++) {
            int p1 = row0 + mr * 16 + tr, p2 = p1 + 8;
#pragma unroll
            for (int nt = 0; nt < 8; nt++) {
                int o = col0 + nt * 8 + tc;
                float b0 = bias[o], b1 = bias[o + 1];
                __nv_bfloat162 v01 = __floats2bfloat162_rn(acc[mr][nt][0] + b0,
                                                           acc[mr][nt][1] + b1);
                __nv_bfloat162 v23 = __floats2bfloat162_rn(acc[mr][nt][2] + b0,
                                                           acc[mr][nt][3] + b1);
                *(__nv_bfloat162*)(Cb + (size_t)p1 * CC + o) = v01;
                *(__nv_bfloat162*)(Cb + (size_t)p2 * CC + o) = v23;
            }
        }
    } else if (MODE == 1) {
        float* Sb = (float*)Cout + (size_t)b * ((size_t)PP * PP);
#pragma unroll
        for (int mr = 0; mr < 2; mr++) {
            int p1 = row0 + mr * 16 + tr, p2 = p1 + 8;
#pragma unroll
            for (int nt = 0; nt < 8; nt++) {
                int n = col0 + nt * 8 + tc;
                *(float2*)(Sb + (size_t)p1 * PP + n) =
                    make_float2(acc[mr][nt][0], acc[mr][nt][1]);
                *(float2*)(Sb + (size_t)p2 * PP + n) =
                    make_float2(acc[mr][nt][2], acc[mr][nt][3]);
            }
        }
    } else {
        float* outp = (float*)Cout;
        const float* xb = xres + (size_t)b * ((size_t)CC * PP);
        float* ob = outp + (size_t)b * ((size_t)CC * PP);
#pragma unroll
        for (int mr = 0; mr < 2; mr++) {
            int p1 = row0 + mr * 16 + tr, p2 = p1 + 8;
            float dg1 = dgv[b * PP + p1], dg2 = dgv[b * PP + p2];
#pragma unroll
            for (int nt = 0; nt < 8; nt++) {
                int o = col0 + nt * 8 + tc;
                float bv0 = bias[o], bv1 = bias[o + 1];
                size_t i01 = (size_t)o * PP + p1;
                size_t i02 = (size_t)o * PP + p2;
                ob[i01]      = xb[i01]      + bv0 + dg1 * acc[mr][nt][0];
                ob[i01 + PP] = xb[i01 + PP] + bv1 + dg1 * acc[mr][nt][1];
                ob[i02]      = xb[i02]      + bv0 + dg2 * acc[mr][nt][2];
                ob[i02 + PP] = xb[i02 + PP] + bv1 + dg2 * acc[mr][nt][3];
            }
        }
    }
}

// ---------------------------------------------------------------------------
// Softmax denominators + diag gather
// ---------------------------------------------------------------------------
__global__ void softmax_diag_kernel(const float* __restrict__ S,
                                    float* __restrict__ diag)
{
    const float scale = 0.04419417382415922f;   // 512^-0.5
    int b = blockIdx.x >> 5;
    int i = blockIdx.x & 31;
    const float* Sb = S + (size_t)b * PP * PP;

    __shared__ float num_sh[32];
    __shared__ float red[256];

    float acc = 0.f;
    for (int h = 0; h < 32; h++) {
        const float* row = Sb + (size_t)(h * 32 + i) * PP;
        bool diag_row = (h == i);
        for (int p = threadIdx.x; p < PP; p += 256) {
            float e = __expf(scale * row[p]);
            acc += e;
            if (diag_row && ((p >> 5) == (p & 31)))
                num_sh[p & 31] = e;   // p == 33*j
        }
    }
    red[threadIdx.x] = acc;
    __syncthreads();
    for (int off = 128; off >= 32; off >>= 1) {
        if (threadIdx.x < off) red[threadIdx.x] += red[threadIdx.x + off];
        __syncthreads();
    }
    if (threadIdx.x < 32)
        diag[(size_t)blockIdx.x * 32 + threadIdx.x] =
            num_sh[threadIdx.x] / red[threadIdx.x];
}

// ---------------------------------------------------------------------------
// kernel_launch — inputs: x, Wq, bq, Wk, bk, Wv, bv, Wn, bn
// ---------------------------------------------------------------------------
extern "C" void kernel_launch(void* const* d_in, const int* in_sizes, int n_in,
                              void* d_out, int out_size)
{
    const float* x  = (const float*)d_in[0];
    const float* Wq = (const float*)d_in[1];
    const float* bq = (const float*)d_in[2];
    const float* Wk = (const float*)d_in[3];
    const float* bk = (const float*)d_in[4];
    const float* Wv = (const float*)d_in[5];
    const float* bv = (const float*)d_in[6];
    const float* Wn = (const float*)d_in[7];
    const float* bn = (const float*)d_in[8];
    float* out = (float*)d_out;

    bf16 *pnT, *pqT, *pkT, *pvT, *pWT;
    float *pS, *pdiag;
    cudaGetSymbolAddress((void**)&pnT, g_nT);
    cudaGetSymbolAddress((void**)&pqT, g_qT);
    cudaGetSymbolAddress((void**)&pkT, g_kT);
    cudaGetSymbolAddress((void**)&pvT, g_vT);
    cudaGetSymbolAddress((void**)&pWT, g_WT);
    cudaGetSymbolAddress((void**)&pS, g_S);
    cudaGetSymbolAddress((void**)&pdiag, g_diag);

    cudaFuncSetAttribute(gemm_mma<0>, cudaFuncAttributeMaxDynamicSharedMemorySize, SMEM_BYTES);
    cudaFuncSetAttribute(gemm_mma<1>, cudaFuncAttributeMaxDynamicSharedMemorySize, SMEM_BYTES);
    cudaFuncSetAttribute(gemm_mma<2>, cudaFuncAttributeMaxDynamicSharedMemorySize, SMEM_BYTES);

    // 1. Weight transposes -> bf16
    wt_kernel<<<dim3(16, 16, 4), dim3(32, 8)>>>(Wq, Wk, Wv, Wn, pWT);

    // 2. GroupNorm -> nT bf16
    gn_kernel<<<BB * 32, 256>>>(x, pnT);

    // 3. Projections
    dim3 gp(8, 4, BB);
    gemm_mma<0><<<gp, 256, SMEM_BYTES>>>(pnT, pWT,               0, pqT, bq, nullptr, nullptr);
    gemm_mma<0><<<gp, 256, SMEM_BYTES>>>(pnT, pWT + CC * CC,     0, pkT, bk, nullptr, nullptr);
    gemm_mma<0><<<gp, 256, SMEM_BYTES>>>(pnT, pWT + 2 * CC * CC, 0, pvT, bv, nullptr, nullptr);

    // 4. Scores
    dim3 gs(8, 8, BB);
    gemm_mma<1><<<gs, 256, SMEM_BYTES>>>(pqT, pkT, (long long)PP * CC, pS,
                                         nullptr, nullptr, nullptr);

    // 5. Softmax denominators + diag
    softmax_diag_kernel<<<BB * 32, 256>>>(pS, pdiag);

    // 6. Final fused projection
    gemm_mma<2><<<gp, 256, SMEM_BYTES>>>(pvT, pWT + 3 * CC * CC, 0, out, bn, x, pdiag);
}

// round 4
// speedup vs baseline: 6.2786x; 1.2809x over previous
#include <cuda_runtime.h>
#include <cuda_bf16.h>
#include <cstdint>

#define BB 16
#define CC 512
#define PP 1024
#define OC 1536   // concatenated q|k|v output channels

typedef __nv_bfloat16 bf16;

// ---------------------------------------------------------------------------
// Static device scratch
// ---------------------------------------------------------------------------
__device__ __align__(1024) bf16 g_nT[(size_t)BB * PP * CC];     // [b][p][c]
__device__ __align__(1024) bf16 g_qkvT[(size_t)BB * PP * OC];   // [b][p][o] o in 0..1536
__device__ __align__(1024) bf16 g_WT[4 * CC * CC];              // [which][o][c]
__device__ __align__(128)  float g_part[(size_t)BB * 64 * 1024]; // per-tile denom partials
__device__ __align__(128)  float g_num[BB * 1024];
__device__ __align__(128)  float g_diag[BB * PP];
__device__ __align__(128)  float g_bcat[OC];

// ---------------------------------------------------------------------------
// helpers
// ---------------------------------------------------------------------------
__device__ __forceinline__ uint32_t smem_u32(const void* p) {
    uint32_t a;
    asm("{ .reg .u64 t; cvta.to.shared.u64 t, %1; cvt.u32.u64 %0, t; }"
        : "=r"(a) : "l"(p));
    return a;
}

#define CPA16(sm, gm) \
    asm volatile("cp.async.cg.shared.global [%0], [%1], 16;" \
                 :: "r"(sm), "l"(gm))

__device__ __forceinline__ void ldsm4(uint32_t* r, uint32_t a) {
    asm volatile("ldmatrix.sync.aligned.m8n8.x4.shared.b16 {%0,%1,%2,%3}, [%4];"
                 : "=r"(r[0]), "=r"(r[1]), "=r"(r[2]), "=r"(r[3]) : "r"(a));
}

__device__ __forceinline__ void mma16816(float* c, const uint32_t* a,
                                         uint32_t b0, uint32_t b1) {
    asm volatile(
        "mma.sync.aligned.m16n8k16.row.col.f32.bf16.bf16.f32 "
        "{%0,%1,%2,%3}, {%4,%5,%6,%7}, {%8,%9}, {%0,%1,%2,%3};"
        : "+f"(c[0]), "+f"(c[1]), "+f"(c[2]), "+f"(c[3])
        : "r"(a[0]), "r"(a[1]), "r"(a[2]), "r"(a[3]), "r"(b0), "r"(b1));
}

// smem tile: 128 rows x 80 bytes (64B data + 16B pad) -> conflict-free ldmatrix
#define ROWB   80
#define TILEB  (128 * ROWB)
#define STAGES 3
#define SMEM_BYTES (STAGES * 2 * TILEB)   // 61440

// ---------------------------------------------------------------------------
// Weight transpose: WT[o][c] = bf16(W[c][o]); which-major = q|k|v|n concat
// ---------------------------------------------------------------------------
__global__ void wt_kernel(const float* __restrict__ Wq, const float* __restrict__ Wk,
                          const float* __restrict__ Wv, const float* __restrict__ Wn,
                          bf16* __restrict__ WT)
{
    const float* srcs[4] = {Wq, Wk, Wv, Wn};
    const float* W = srcs[blockIdx.z];
    bf16* dst = WT + (size_t)blockIdx.z * CC * CC;
    __shared__ float t[32][33];
    int c0 = blockIdx.x * 32, o0 = blockIdx.y * 32;
    for (int i = threadIdx.y; i < 32; i += 8)
        t[i][threadIdx.x] = W[(size_t)(c0 + i) * CC + o0 + threadIdx.x];
    __syncthreads();
    for (int i = threadIdx.y; i < 32; i += 8)
        dst[(size_t)(o0 + i) * CC + c0 + threadIdx.x] =
            __float2bfloat16(t[threadIdx.x][i]);
}

__global__ void bcat_kernel(const float* __restrict__ bq, const float* __restrict__ bk,
                            const float* __restrict__ bv, float* __restrict__ bc)
{
    int i = blockIdx.x * 256 + threadIdx.x;
    if (i < CC) {
        bc[i] = bq[i];
        bc[CC + i] = bk[i];
        bc[2 * CC + i] = bv[i];
    }
}

// ---------------------------------------------------------------------------
// GroupNorm -> transposed bf16 output nT[b][p][c]
// ---------------------------------------------------------------------------
__global__ void gn_kernel(const float* __restrict__ x, bf16* __restrict__ nT)
{
    int b = blockIdx.x >> 5;
    int g = blockIdx.x & 31;
    const float* xp = x + ((size_t)b * CC + g * 16) * PP;

    float s = 0.f, s2 = 0.f;
    for (int i = threadIdx.x; i < 16384; i += 256) {
        float v = xp[i];
        s += v; s2 += v * v;
    }
    __shared__ float sh1[256], sh2[256];
    sh1[threadIdx.x] = s; sh2[threadIdx.x] = s2;
    __syncthreads();
    for (int off = 128; off; off >>= 1) {
        if (threadIdx.x < off) {
            sh1[threadIdx.x] += sh1[threadIdx.x + off];
            sh2[threadIdx.x] += sh2[threadIdx.x + off];
        }
        __syncthreads();
    }
    float mean = sh1[0] * (1.f / 16384.f);
    float var  = sh2[0] * (1.f / 16384.f) - mean * mean;
    float inv  = rsqrtf(var + 1e-5f);

    bf16* np = nT + (size_t)b * PP * CC + g * 16;
    for (int p = threadIdx.x; p < PP; p += 256) {
        uint32_t pk[8];
#pragma unroll
        for (int cc = 0; cc < 16; cc += 2) {
            float v0 = (xp[(size_t)cc * PP + p] - mean) * inv;
            float v1 = (xp[(size_t)(cc + 1) * PP + p] - mean) * inv;
            __nv_bfloat162 h = __floats2bfloat162_rn(v0, v1);
            pk[cc >> 1] = *(uint32_t*)&h;
        }
        uint4* dst = (uint4*)(np + (size_t)p * CC);
        dst[0] = make_uint4(pk[0], pk[1], pk[2], pk[3]);
        dst[1] = make_uint4(pk[4], pk[5], pk[6], pk[7]);
    }
}

// ---------------------------------------------------------------------------
// HMMA GEMM: D[m][n] = sum_{k<512} A[m][k]*B[n][k]; runtime row strides.
// CTA 128x128, warp 32x64, K slab 32, 3-stage cp.async.
// MODE 0: bf16 C[p][o] = D + bias[o], ldc=1536                (merged q|k|v proj)
// MODE 1: fused exp epilogue -> g_part / g_num (no D written) (scores)
// MODE 2: fp32 out[o][p] = x + bias[o] + diag[p]*D, smem-transposed (final)
// ---------------------------------------------------------------------------
template <int MODE>
__global__ __launch_bounds__(256)
void gemm_mma(const bf16* __restrict__ A, long long sA, int ldaA,
              const bf16* __restrict__ Bm, long long sB, int ldaB,
              void* __restrict__ Cout,
              const float* __restrict__ bias, const float* __restrict__ xres,
              const float* __restrict__ dgv,
              float* __restrict__ part, float* __restrict__ num)
{
    extern __shared__ char smem[];
    uint32_t s0 = smem_u32(smem);

    int tid = threadIdx.x, lane = tid & 31, wid = tid >> 5;
    int wm = wid & 3, wn = wid >> 2;
    int b = blockIdx.z;
    int m0 = blockIdx.x * 128, n0 = blockIdx.y * 128;

    const char* Ab = (const char*)A + ((size_t)b * sA + (size_t)m0 * ldaA) * 2;
    const char* Bb = (const char*)Bm + ((size_t)b * sB + (size_t)n0 * ldaB) * 2;

    int ra0 = tid >> 2, ca0 = tid & 3;
    int ra1 = (tid + 256) >> 2, ca1 = (tid + 256) & 3;
    uint32_t sm0 = (uint32_t)(ra0 * ROWB + ca0 * 16);
    uint32_t sm1 = (uint32_t)(ra1 * ROWB + ca1 * 16);
    int gA0 = ra0 * ldaA * 2 + ca0 * 16;
    int gA1 = ra1 * ldaA * 2 + ca1 * 16;
    int gB0 = ra0 * ldaB * 2 + ca0 * 16;
    int gB1 = ra1 * ldaB * 2 + ca1 * 16;

    uint32_t aoff[2][2], boff[2][4];
    {
        int ar = wm * 32 + (lane & 15);
        int ac = (lane >> 4);
#pragma unroll
        for (int mr = 0; mr < 2; mr++)
#pragma unroll
            for (int ks = 0; ks < 2; ks++)
                aoff[mr][ks] = (uint32_t)((ar + mr * 16) * ROWB + (ks * 2 + ac) * 16);
        int br = wn * 64 + ((lane >> 4) & 1) * 8 + (lane & 7);
        int bc = (lane >> 3) & 1;
#pragma unroll
        for (int ks = 0; ks < 2; ks++)
#pragma unroll
            for (int p = 0; p < 4; p++)
                boff[ks][p] = (uint32_t)((br + p * 16) * ROWB + (ks * 2 + bc) * 16);
    }

    float acc[2][8][4];
#pragma unroll
    for (int i = 0; i < 2; i++)
#pragma unroll
        for (int j = 0; j < 8; j++)
#pragma unroll
            for (int l = 0; l < 4; l++) acc[i][j][l] = 0.f;

    auto issue = [&](int s, int st) {
        uint32_t ab = s0 + (uint32_t)st * (2 * TILEB);
        uint32_t bb = ab + TILEB;
        const char* ga = Ab + s * 64;
        const char* gb = Bb + s * 64;
        CPA16(ab + sm0, ga + gA0);
        CPA16(ab + sm1, ga + gA1);
        CPA16(bb + sm0, gb + gB0);
        CPA16(bb + sm1, gb + gB1);
        asm volatile("cp.async.commit_group;" ::: "memory");
    };

    issue(0, 0);
    issue(1, 1);

    for (int s = 0; s < 16; s++) {
        if (s < 15) asm volatile("cp.async.wait_group 1;" ::: "memory");
        else        asm volatile("cp.async.wait_group 0;" ::: "memory");
        __syncthreads();
        if (s + 2 < 16) issue(s + 2, (s + 2) % 3);

        uint32_t ab = s0 + (uint32_t)(s % 3) * (2 * TILEB);
        uint32_t bb = ab + TILEB;

#pragma unroll
        for (int ks = 0; ks < 2; ks++) {
            uint32_t af[2][4], bfr[4][4];
            ldsm4(af[0], ab + aoff[0][ks]);
            ldsm4(af[1], ab + aoff[1][ks]);
#pragma unroll
            for (int p = 0; p < 4; p++)
                ldsm4(bfr[p], bb + boff[ks][p]);
#pragma unroll
            for (int mr = 0; mr < 2; mr++)
#pragma unroll
                for (int nt = 0; nt < 8; nt++)
                    mma16816(acc[mr][nt], af[mr],
                             bfr[nt >> 1][(nt & 1) * 2], bfr[nt >> 1][(nt & 1) * 2 + 1]);
        }
        __syncthreads();
    }

    // ---------------- epilogues ----------------
    int row0 = m0 + wm * 32;
    int col0 = n0 + wn * 64;
    int tr = lane >> 2, tc = (lane & 3) * 2;

    if (MODE == 0) {
        bf16* Cb = (bf16*)Cout + (size_t)b * ((size_t)PP * OC);
#pragma unroll
        for (int mr = 0; mr < 2; mr++) {
            int p1 = row0 + mr * 16 + tr, p2 = p1 + 8;
#pragma unroll
            for (int nt = 0; nt < 8; nt++) {
                int o = col0 + nt * 8 + tc;
                float b0 = bias[o], b1 = bias[o + 1];
                __nv_bfloat162 v01 = __floats2bfloat162_rn(acc[mr][nt][0] + b0,
                                                           acc[mr][nt][1] + b1);
                __nv_bfloat162 v23 = __floats2bfloat162_rn(acc[mr][nt][2] + b0,
                                                           acc[mr][nt][3] + b1);
                *(__nv_bfloat162*)(Cb + (size_t)p1 * OC + o) = v01;
                *(__nv_bfloat162*)(Cb + (size_t)p2 * OC + o) = v23;
            }
        }
    } else if (MODE == 1) {
        // exp + numerator capture + deterministic per-tile denom partials
        const float scale = 0.04419417382415922f;   // 512^-0.5
#pragma unroll
        for (int mr = 0; mr < 2; mr++)
#pragma unroll
            for (int nt = 0; nt < 8; nt++)
#pragma unroll
                for (int l = 0; l < 4; l++) {
                    float e = __expf(scale * acc[mr][nt][l]);
                    acc[mr][nt][l] = e;
                    int p = row0 + mr * 16 + tr + ((l >> 1) * 8);
                    int n = col0 + nt * 8 + tc + (l & 1);
                    if (((p >> 5) == (p & 31)) && ((n >> 5) == (n & 31)))
                        num[b * 1024 + (p & 31) * 32 + (n & 31)] = e;
                }
        float* sp = (float*)smem;   // 8 warps x 1024 bins = 32KB
#pragma unroll
        for (int mr = 0; mr < 2; mr++)
#pragma unroll
            for (int rt = 0; rt < 2; rt++) {
                int i = mr * 16 + tr + rt * 8;
#pragma unroll
                for (int nt4 = 0; nt4 < 4; nt4++)
#pragma unroll
                    for (int ct = 0; ct < 2; ct++) {
                        int j = nt4 * 8 + tc + ct;
                        sp[wid * 1024 + i * 32 + j] =
                            acc[mr][nt4][rt * 2 + ct] + acc[mr][nt4 + 4][rt * 2 + ct];
                    }
            }
        __syncthreads();
        float* pb = part + ((size_t)(b * 64 + blockIdx.y * 8 + blockIdx.x)) * 1024;
        for (int ij = tid; ij < 1024; ij += 256) {
            float sum = 0.f;
#pragma unroll
            for (int w = 0; w < 8; w++) sum += sp[w * 1024 + ij];
            pb[ij] = sum;
        }
    } else {
        // MODE 2: transpose through smem, coalesced fp32 writes
        float* ob = (float*)Cout + (size_t)b * ((size_t)CC * PP);
        const float* xb = xres + (size_t)b * ((size_t)CC * PP);
        float dg1[2], dg2[2];
#pragma unroll
        for (int mr = 0; mr < 2; mr++) {
            dg1[mr] = dgv[b * PP + row0 + mr * 16 + tr];
            dg2[mr] = dgv[b * PP + row0 + mr * 16 + tr + 8];
        }
        float (*tp)[132] = (float(*)[132])smem;
        for (int h = 0; h < 2; h++) {
            __syncthreads();
            if (wn == h) {
#pragma unroll
                for (int mr = 0; mr < 2; mr++)
#pragma unroll
                    for (int nt = 0; nt < 8; nt++)
#pragma unroll
                        for (int l = 0; l < 4; l++) {
                            int o_in = nt * 8 + tc + (l & 1);
                            int p_l = wm * 32 + mr * 16 + tr + ((l >> 1) * 8);
                            float dg = (l >> 1) ? dg2[mr] : dg1[mr];
                            tp[o_in][p_l] = dg * acc[mr][nt][l];
                        }
            }
            __syncthreads();
            int r = tid >> 2;
            int cb = (tid & 3) * 32;
            int o = n0 + h * 64 + r;
            float bv = bias[o];
            size_t base = (size_t)o * PP + m0;
#pragma unroll
            for (int k = 0; k < 8; k++) {
                int c = cb + k * 4;
                float4 xv = *(const float4*)(xb + base + c);
                float4 w;
                w.x = xv.x + bv + tp[r][c];
                w.y = xv.y + bv + tp[r][c + 1];
                w.z = xv.z + bv + tp[r][c + 2];
                w.w = xv.w + bv + tp[r][c + 3];
                *(float4*)(ob + base + c) = w;
            }
        }
    }
}

// ---------------------------------------------------------------------------
// diag = num / sum(part)   (deterministic fixed-order sum over 64 tiles)
// ---------------------------------------------------------------------------
__global__ void diag_kernel(const float* __restrict__ part,
                            const float* __restrict__ num,
                            float* __restrict__ diag)
{
    int idx = blockIdx.x * 256 + threadIdx.x;   // 16384 total
    int b = idx >> 10, ij = idx & 1023;
    const float* pp = part + (size_t)b * 64 * 1024 + ij;
    float s = 0.f;
#pragma unroll
    for (int t = 0; t < 64; t++) s += pp[t * 1024];
    diag[idx] = num[idx] / s;
}

// ---------------------------------------------------------------------------
// kernel_launch — inputs: x, Wq, bq, Wk, bk, Wv, bv, Wn, bn
// ---------------------------------------------------------------------------
extern "C" void kernel_launch(void* const* d_in, const int* in_sizes, int n_in,
                              void* d_out, int out_size)
{
    const float* x  = (const float*)d_in[0];
    const float* Wq = (const float*)d_in[1];
    const float* bq = (const float*)d_in[2];
    const float* Wk = (const float*)d_in[3];
    const float* bk = (const float*)d_in[4];
    const float* Wv = (const float*)d_in[5];
    const float* bv = (const float*)d_in[6];
    const float* Wn = (const float*)d_in[7];
    const float* bn = (const float*)d_in[8];
    float* out = (float*)d_out;

    bf16 *pnT, *pqkv, *pWT;
    float *ppart, *pnum, *pdiag, *pbcat;
    cudaGetSymbolAddress((void**)&pnT, g_nT);
    cudaGetSymbolAddress((void**)&pqkv, g_qkvT);
    cudaGetSymbolAddress((void**)&pWT, g_WT);
    cudaGetSymbolAddress((void**)&ppart, g_part);
    cudaGetSymbolAddress((void**)&pnum, g_num);
    cudaGetSymbolAddress((void**)&pdiag, g_diag);
    cudaGetSymbolAddress((void**)&pbcat, g_bcat);

    cudaFuncSetAttribute(gemm_mma<0>, cudaFuncAttributeMaxDynamicSharedMemorySize, SMEM_BYTES);
    cudaFuncSetAttribute(gemm_mma<1>, cudaFuncAttributeMaxDynamicSharedMemorySize, SMEM_BYTES);
    cudaFuncSetAttribute(gemm_mma<2>, cudaFuncAttributeMaxDynamicSharedMemorySize, SMEM_BYTES);

    // 1. Weight transposes + bias concat
    wt_kernel<<<dim3(16, 16, 4), dim3(32, 8)>>>(Wq, Wk, Wv, Wn, pWT);
    bcat_kernel<<<2, 256>>>(bq, bk, bv, pbcat);

    // 2. GroupNorm -> nT bf16
    gn_kernel<<<BB * 32, 256>>>(x, pnT);

    // 3. Merged q|k|v projection: C[p][0..1536) = nT @ WTcat^T + bcat
    dim3 gp(8, 12, BB);
    gemm_mma<0><<<gp, 256, SMEM_BYTES>>>(pnT, (long long)PP * CC, CC,
                                         pWT, 0, CC,
                                         pqkv, pbcat, nullptr, nullptr,
                                         nullptr, nullptr);

    // 4. Scores with fused exp epilogue (no S materialization)
    dim3 gs(8, 8, BB);
    gemm_mma<1><<<gs, 256, SMEM_BYTES>>>(pqkv, (long long)PP * OC, OC,
                                         pqkv + CC, (long long)PP * OC, OC,
                                         nullptr, nullptr, nullptr, nullptr,
                                         ppart, pnum);

    // 5. diag = num / denom
    diag_kernel<<<64, 256>>>(ppart, pnum, pdiag);

    // 6. Final fused projection (smem-transposed coalesced output)
    dim3 gf(8, 4, BB);
    gemm_mma<2><<<gf, 256, SMEM_BYTES>>>(pqkv + 2 * CC, (long long)PP * OC, OC,
                                         pWT + 3 * CC * CC, 0, CC,
                                         out, bn, x, pdiag,
                                         nullptr, nullptr);
}